// round 7
// baseline (speedup 1.0000x reference)
#include <cuda_runtime.h>
#include <cuda_bf16.h>
#include <math.h>
#include <stdint.h>

#define N 4096
#define D 512
#define MARGIN 0.3f
#define BIG 1000000.0f
#define NT 32                       // 4096/128 tile grid
#define NBLK (NT * (NT + 1) / 2)    // 528 upper-triangular tiles

// ---------------- scratch (no allocs allowed) ----------------
__device__ float g_dist[(size_t)N * N];            // d2, upper-tri tiles only
__device__ __nv_bfloat16 g_hi[(size_t)N * D];
__device__ __nv_bfloat16 g_lo[(size_t)N * D];
__device__ float g_sq[N];
__device__ int   g_hp_bits[N];                     // hp^2 bits (atomicMax)
__device__ int   g_fb_bits[N];                     // fb^2 bits
__device__ int   g_smin_bits[N];                   // semi-hard min d2 bits (atomicMin)
__device__ int   g_scnt_row[N];                    // per-row semi-hard count
__device__ int   g_done;

// ---------------- PTX helpers ----------------
__device__ __forceinline__ uint32_t smem_u32(const void* p) {
    return (uint32_t)__cvta_generic_to_shared(p);
}
__device__ __forceinline__ void cp16(uint32_t dst, const void* src) {
    asm volatile("cp.async.cg.shared.global [%0], [%1], 16;" :: "r"(dst), "l"(src));
}
#define LDSM4(r0, r1, r2, r3, addr)                                          \
    asm volatile("ldmatrix.sync.aligned.m8n8.x4.shared.b16 {%0,%1,%2,%3}, [%4];" \
                 : "=r"(r0), "=r"(r1), "=r"(r2), "=r"(r3) : "r"(addr))
#define MMA_BF16(acc, a, b)                                                  \
    asm volatile("mma.sync.aligned.m16n8k16.row.col.f32.bf16.bf16.f32 "      \
                 "{%0,%1,%2,%3}, {%4,%5,%6,%7}, {%8,%9}, {%0,%1,%2,%3};"     \
                 : "+f"((acc)[0]), "+f"((acc)[1]), "+f"((acc)[2]), "+f"((acc)[3]) \
                 : "r"((a)[0]), "r"((a)[1]), "r"((a)[2]), "r"((a)[3]),       \
                   "r"((b)[0]), "r"((b)[1]))

// ---------------- 1: prep — warp-per-row bf16 split + sq-norms + init ----------------
__global__ __launch_bounds__(256) void prep_kernel(const float* __restrict__ E) {
    const int w = threadIdx.x >> 5, lane = threadIdx.x & 31;
    const int row = blockIdx.x * 8 + w;
    const float* __restrict__ src = E + (size_t)row * D;
    float s = 0.0f;
#pragma unroll
    for (int q = 0; q < 4; q++) {
        const int col = (lane + 32 * q) * 4;
        const float4 v = *(const float4*)&src[col];
        const float f[4] = {v.x, v.y, v.z, v.w};
        uint32_t hp[2], lp[2];
#pragma unroll
        for (int p = 0; p < 2; p++) {
            const float a = f[2 * p], b = f[2 * p + 1];
            s += a * a + b * b;
            const __nv_bfloat16 ha = __float2bfloat16(a);
            const __nv_bfloat16 hb = __float2bfloat16(b);
            const __nv_bfloat16 la = __float2bfloat16(a - __bfloat162float(ha));
            const __nv_bfloat16 lb = __float2bfloat16(b - __bfloat162float(hb));
            hp[p] = ((uint32_t)__bfloat16_as_ushort(hb) << 16) | __bfloat16_as_ushort(ha);
            lp[p] = ((uint32_t)__bfloat16_as_ushort(lb) << 16) | __bfloat16_as_ushort(la);
        }
        *(uint2*)&g_hi[(size_t)row * D + col] = make_uint2(hp[0], hp[1]);
        *(uint2*)&g_lo[(size_t)row * D + col] = make_uint2(lp[0], lp[1]);
    }
    for (int o = 16; o > 0; o >>= 1) s += __shfl_down_sync(0xFFFFFFFF, s, o);
    if (lane == 0) {
        g_sq[row] = s;
        g_hp_bits[row] = 0;
        g_fb_bits[row] = 0;
        g_smin_bits[row] = 0x7F7FFFFF;      // FLT_MAX bits
        g_scnt_row[row] = 0;
    }
    if (blockIdx.x == 0 && threadIdx.x == 0) g_done = 0;
}

// ---------------- 2: symmetric bf16 split-GEMM -> d2 upper tile + hp2/fb2 (both roles) ----------------
#define BM 128
#define BN 128
#define KS 16                    // 512 / 32
#define ROWB 80                  // 32 bf16 = 64B + 16B pad
#define TILEB (128 * ROWB)       // 10240 per tile
#define SM_LJ 0
#define SM_LI 512
#define SM_SQJ 1024
#define SM_SQI 1536
#define SM_OPS 2048
#define GEMM_SMEM (SM_OPS + 8 * TILEB)     // 83968
#define STG_STRIDE 132

__global__ __launch_bounds__(256) void gemm_bf16(const int* __restrict__ labels) {
    extern __shared__ char smem[];
    const int tid = threadIdx.x, lane = tid & 31, wid = tid >> 5;
    const int wm = wid >> 2, wn = wid & 3;          // 2 x 4 warp grid
    const int gid = lane >> 2, tig = lane & 3;

    // map linear block id -> upper-triangular tile (bi <= bj)
    int b = blockIdx.x, bi = 0;
    while (b >= NT - bi) { b -= NT - bi; bi++; }
    const int bj = bi + b;
    const int i0 = bi * BM, j0 = bj * BN;
    const bool diag = (bi == bj);

    const uint32_t sb = smem_u32(smem);
    int*   lj  = (int*)(smem + SM_LJ);
    int*   li  = (int*)(smem + SM_LI);
    float* sqj = (float*)(smem + SM_SQJ);
    float* sqi = (float*)(smem + SM_SQI);
    if (tid < 128) { lj[tid] = labels[j0 + tid]; sqj[tid] = g_sq[j0 + tid]; }
    else { const int t2 = tid - 128; li[t2] = labels[i0 + t2]; sqi[t2] = g_sq[i0 + t2]; }

    float acc[4][4][4];
#pragma unroll
    for (int mt = 0; mt < 4; mt++)
#pragma unroll
        for (int nt = 0; nt < 4; nt++)
#pragma unroll
            for (int k = 0; k < 4; k++) acc[mt][nt][k] = 0.0f;

    auto load_stage = [&](int st, int k0e) {
        const uint32_t base = sb + SM_OPS + ((st & 1) ? 4 * TILEB : 0);
#pragma unroll
        for (int i = 0; i < 8; i++) {
            const int idx = tid + i * 256;
            const int tile = idx >> 9;          // 0:Ah 1:Al 2:Bh 3:Bl
            const int id = idx & 511;
            const int r = id >> 2, c = id & 3;
            const int grow = ((tile >= 2) ? j0 : i0) + r;
            const __nv_bfloat16* src =
                ((tile & 1) ? g_lo : g_hi) + (size_t)grow * D + k0e + c * 8;
            cp16(base + tile * TILEB + r * ROWB + c * 16, src);
        }
    };

    load_stage(0, 0);
    asm volatile("cp.async.commit_group;" ::: "memory");

    for (int t = 0; t < KS; t++) {
        if (t + 1 < KS) {
            load_stage(t + 1, (t + 1) * 32);
            asm volatile("cp.async.commit_group;" ::: "memory");
            asm volatile("cp.async.wait_group 1;" ::: "memory");
        } else {
            asm volatile("cp.async.wait_group 0;" ::: "memory");
        }
        __syncthreads();

        const uint32_t base = sb + SM_OPS + ((t & 1) ? 4 * TILEB : 0);
        const uint32_t Ah = base, Al = base + TILEB;
        const uint32_t Bh = base + 2 * TILEB, Bl = base + 3 * TILEB;
        const uint32_t arow = (wm * 64 + (lane & 15)) * ROWB + (lane >> 4) * 16;
        const uint32_t brow = (wn * 32 + (lane & 15)) * ROWB + (lane >> 4) * 16;

#pragma unroll
        for (int kk = 0; kk < 2; kk++) {
            uint32_t ah[4][4], al_[4][4], bh[4][2], bl[4][2];
#pragma unroll
            for (int mt = 0; mt < 4; mt++) {
                const uint32_t off = arow + mt * 16 * ROWB + kk * 32;
                LDSM4(ah[mt][0], ah[mt][1], ah[mt][2], ah[mt][3], Ah + off);
                LDSM4(al_[mt][0], al_[mt][1], al_[mt][2], al_[mt][3], Al + off);
            }
#pragma unroll
            for (int p = 0; p < 2; p++) {
                const uint32_t off = brow + p * 16 * ROWB + kk * 32;
                uint32_t r0, r1, r2, r3;
                LDSM4(r0, r1, r2, r3, Bh + off);
                bh[p * 2][0] = r0; bh[p * 2][1] = r2;
                bh[p * 2 + 1][0] = r1; bh[p * 2 + 1][1] = r3;
                LDSM4(r0, r1, r2, r3, Bl + off);
                bl[p * 2][0] = r0; bl[p * 2][1] = r2;
                bl[p * 2 + 1][0] = r1; bl[p * 2 + 1][1] = r3;
            }
#pragma unroll
            for (int mt = 0; mt < 4; mt++)
#pragma unroll
                for (int nt = 0; nt < 4; nt++) {
                    MMA_BF16(acc[mt][nt], ah[mt], bh[nt]);   // hi*hi
                    MMA_BF16(acc[mt][nt], ah[mt], bl[nt]);   // hi*lo
                    MMA_BF16(acc[mt][nt], al_[mt], bh[nt]);  // lo*hi
                }
        }
        __syncthreads();
    }

    // ---- stage fp32 dots to smem (read-only afterwards) ----
    float* stg = (float*)(smem + SM_OPS);
#pragma unroll
    for (int mt = 0; mt < 4; mt++)
#pragma unroll
        for (int nt = 0; nt < 4; nt++) {
            const int r0 = wm * 64 + mt * 16 + gid;
            const int c0 = wn * 32 + nt * 8 + tig * 2;
            *(float2*)&stg[r0 * STG_STRIDE + c0] = make_float2(acc[mt][nt][0], acc[mt][nt][1]);
            *(float2*)&stg[(r0 + 8) * STG_STRIDE + c0] = make_float2(acc[mt][nt][2], acc[mt][nt][3]);
        }
    __syncthreads();

    // ---- row pass: d2, store [i,j] tile, hp2/fb2 for i-rows ----
#pragma unroll 1
    for (int rr = 0; rr < 16; rr++) {
        const int row = wid * 16 + rr;
        const float4 v = *(const float4*)&stg[row * STG_STRIDE + lane * 4];
        const float sqiv = sqi[row];
        const int liv = li[row];
        float hp = 0.0f, fb = 0.0f;
        float o[4];
#pragma unroll
        for (int u = 0; u < 4; u++) {
            const int jc = lane * 4 + u;
            const float d2 = fmaxf(fmaf(-2.0f, (&v.x)[u], sqiv + sqj[jc]), 1e-12f);
            o[u] = d2;
            if (lj[jc] == liv) hp = fmaxf(hp, d2);
            else               fb = fmaxf(fb, d2);
        }
        *(float4*)&g_dist[(size_t)(i0 + row) * N + j0 + lane * 4] =
            make_float4(o[0], o[1], o[2], o[3]);
#pragma unroll
        for (int off = 16; off > 0; off >>= 1) {
            hp = fmaxf(hp, __shfl_down_sync(0xFFFFFFFF, hp, off));
            fb = fmaxf(fb, __shfl_down_sync(0xFFFFFFFF, fb, off));
        }
        if (lane == 0) {
            atomicMax(&g_hp_bits[i0 + row], __float_as_int(hp));
            atomicMax(&g_fb_bits[i0 + row], __float_as_int(fb));
        }
    }

    // ---- mirror hp/fb pass (off-diag): float4 column chunks, NO global stores ----
    if (!diag) {
#pragma unroll 1
        for (int jc = 0; jc < 4; jc++) {
            const int j4 = wid * 16 + jc * 4;    // 4 j-anchor rows per chunk
            float hp4[4] = {0, 0, 0, 0}, fb4[4] = {0, 0, 0, 0};
            int   lj4[4];
            float sq4[4];
#pragma unroll
            for (int q = 0; q < 4; q++) { lj4[q] = lj[j4 + q]; sq4[q] = sqj[j4 + q]; }
#pragma unroll
            for (int u = 0; u < 4; u++) {
                const int il = lane + 32 * u;
                const float4 v = *(const float4*)&stg[il * STG_STRIDE + j4];
                const float sqiv = sqi[il];
                const int liv = li[il];
#pragma unroll
                for (int q = 0; q < 4; q++) {
                    const float d2 = fmaxf(fmaf(-2.0f, (&v.x)[q], sqiv + sq4[q]), 1e-12f);
                    if (liv == lj4[q]) hp4[q] = fmaxf(hp4[q], d2);
                    else               fb4[q] = fmaxf(fb4[q], d2);
                }
            }
#pragma unroll
            for (int q = 0; q < 4; q++) {
#pragma unroll
                for (int off = 16; off > 0; off >>= 1) {
                    hp4[q] = fmaxf(hp4[q], __shfl_down_sync(0xFFFFFFFF, hp4[q], off));
                    fb4[q] = fmaxf(fb4[q], __shfl_down_sync(0xFFFFFFFF, fb4[q], off));
                }
                if (lane == 0) {
                    atomicMax(&g_hp_bits[j0 + j4 + q], __float_as_int(hp4[q]));
                    atomicMax(&g_fb_bits[j0 + j4 + q], __float_as_int(fb4[q]));
                }
            }
        }
    }
}

// ---------------- 3: tile-based semi-hard pass over upper-tri + fused finalize ----------------
#define RS_STRIDE 129
#define RS_STG 0                              // 128*129*4 = 66048
#define RS_LI  66048                          // 512
#define RS_LJ  66560                          // 512
#define RS_HPI 67072                          // 512
#define RS_HBI 67584                          // 512
#define RS_HPJ 68096                          // 512
#define RS_HBJ 68608                          // 512
#define RS_SMEM 69632

__global__ __launch_bounds__(256) void rowstats_tiles(const int* __restrict__ labels,
                                                      float* __restrict__ out) {
    extern __shared__ char smem[];
    float* stg  = (float*)(smem + RS_STG);
    int*   li_s = (int*)(smem + RS_LI);
    int*   lj_s = (int*)(smem + RS_LJ);
    float* hp2i = (float*)(smem + RS_HPI);
    float* hb2i = (float*)(smem + RS_HBI);
    float* hp2j = (float*)(smem + RS_HPJ);
    float* hb2j = (float*)(smem + RS_HBJ);

    const int tid = threadIdx.x, lane = tid & 31, wid = tid >> 5;

    int b = blockIdx.x, bi = 0;
    while (b >= NT - bi) { b -= NT - bi; bi++; }
    const int bj = bi + b;
    const int i0 = bi * BM, j0 = bj * BM;
    const bool diag = (bi == bj);

    if (tid < 128) {
        li_s[tid] = labels[i0 + tid];
        const float h2 = __int_as_float(g_hp_bits[i0 + tid]);
        hp2i[tid] = h2;
        const float hb = sqrtf(h2) + MARGIN;
        hb2i[tid] = hb * hb;
    } else {
        const int t2 = tid - 128;
        lj_s[t2] = labels[j0 + t2];
        const float h2 = __int_as_float(g_hp_bits[j0 + t2]);
        hp2j[t2] = h2;
        const float hb = sqrtf(h2) + MARGIN;
        hb2j[t2] = hb * hb;
    }

    // stage tile: scalar loads (coalesced) + scalar STS (conflict-free @ stride 129)
#pragma unroll 4
    for (int idx = tid; idx < 128 * 128; idx += 256) {
        const int r = idx >> 7, c = idx & 127;
        stg[r * RS_STRIDE + c] = g_dist[(size_t)(i0 + r) * N + j0 + c];
    }
    __syncthreads();

    // ---- row pass: anchors i over cols j ----
#pragma unroll 1
    for (int rr = 0; rr < 16; rr++) {
        const int r = wid * 16 + rr;
        const float wlo = hp2i[r], whi = hb2i[r];
        const int al = li_s[r];
        float mn = 3.4e38f;
        int cnt = 0;
#pragma unroll
        for (int k = 0; k < 4; k++) {
            const int c = lane + 32 * k;
            const float d2 = stg[r * RS_STRIDE + c];
            const bool sh = (lj_s[c] != al) && (d2 > wlo) && (d2 < whi);
            if (sh) { mn = fminf(mn, d2); cnt++; }
        }
#pragma unroll
        for (int off = 16; off > 0; off >>= 1) {
            mn = fminf(mn, __shfl_down_sync(0xFFFFFFFF, mn, off));
            cnt += __shfl_down_sync(0xFFFFFFFF, cnt, off);
        }
        if (lane == 0 && cnt > 0) {
            atomicMin(&g_smin_bits[i0 + r], __float_as_int(mn));
            atomicAdd(&g_scnt_row[i0 + r], cnt);
        }
    }

    // ---- col pass (off-diag): anchors j over rows i ----
    if (!diag) {
#pragma unroll 1
        for (int cc = 0; cc < 16; cc++) {
            const int c = wid * 16 + cc;
            const float wlo = hp2j[c], whi = hb2j[c];
            const int al = lj_s[c];
            float mn = 3.4e38f;
            int cnt = 0;
#pragma unroll
            for (int k = 0; k < 4; k++) {
                const int r = lane + 32 * k;
                const float d2 = stg[r * RS_STRIDE + c];
                const bool sh = (li_s[r] != al) && (d2 > wlo) && (d2 < whi);
                if (sh) { mn = fminf(mn, d2); cnt++; }
            }
#pragma unroll
            for (int off = 16; off > 0; off >>= 1) {
                mn = fminf(mn, __shfl_down_sync(0xFFFFFFFF, mn, off));
                cnt += __shfl_down_sync(0xFFFFFFFF, cnt, off);
            }
            if (lane == 0 && cnt > 0) {
                atomicMin(&g_smin_bits[j0 + c], __float_as_int(mn));
                atomicAdd(&g_scnt_row[j0 + c], cnt);
            }
        }
    }

    // ---- done counter; last block finalizes loss ----
    __threadfence();
    __syncthreads();
    __shared__ int s_last;
    if (tid == 0) s_last = (atomicAdd(&g_done, 1) == NBLK - 1) ? 1 : 0;
    __syncthreads();
    if (!s_last) return;
    __threadfence();

    // reuse stg as reduction scratch
    double* rs = (double*)stg;            // 256 doubles
    double* rf = rs + 256;                // 256 doubles
    int* rcs = (int*)(rf + 256);          // 256 ints
    int* rcf = rcs + 256;
    int* rtt = rcf + 256;

    double ss = 0.0, sf = 0.0;
    int cs = 0, cf = 0, tot = 0;
    for (int i = tid; i < N; i += 256) {
        const float hp = sqrtf(__int_as_float(g_hp_bits[i]));
        const int cnt = g_scnt_row[i];
        tot += cnt;
        const float hns = (cnt > 0) ? sqrtf(__int_as_float(g_smin_bits[i])) : BIG;
        const float fbv = sqrtf(__int_as_float(g_fb_bits[i]));
        const float trs = fmaxf(hp - hns + MARGIN, 0.0f);
        const float trf = fmaxf(hp - fbv + MARGIN, 0.0f);
        ss += (double)trs; cs += (trs > 0.0f) ? 1 : 0;
        sf += (double)trf; cf += (trf > 0.0f) ? 1 : 0;
    }
    rs[tid] = ss; rf[tid] = sf; rcs[tid] = cs; rcf[tid] = cf; rtt[tid] = tot;
    __syncthreads();
    for (int s = 128; s > 0; s >>= 1) {
        if (tid < s) {
            rs[tid] += rs[tid + s]; rf[tid] += rf[tid + s];
            rcs[tid] += rcs[tid + s]; rcf[tid] += rcf[tid + s];
            rtt[tid] += rtt[tid + s];
        }
        __syncthreads();
    }
    if (tid == 0) {
        const bool semi = rtt[0] > 0;
        const double s = semi ? rs[0] : rf[0];
        const int c = semi ? rcs[0] : rcf[0];
        out[0] = (float)(s / (double)(c > 0 ? c : 1));
    }
}

// ---------------- launcher ----------------
extern "C" void kernel_launch(void* const* d_in, const int* in_sizes, int n_in,
                              void* d_out, int out_size) {
    const float* E = (const float*)d_in[0];
    const int* labels = (const int*)d_in[1];
    float* out = (float*)d_out;

    cudaFuncSetAttribute(gemm_bf16, cudaFuncAttributeMaxDynamicSharedMemorySize, GEMM_SMEM);
    cudaFuncSetAttribute(rowstats_tiles, cudaFuncAttributeMaxDynamicSharedMemorySize, RS_SMEM);

    prep_kernel<<<N / 8, 256>>>(E);
    gemm_bf16<<<NBLK, 256, GEMM_SMEM>>>(labels);
    rowstats_tiles<<<NBLK, 256, RS_SMEM>>>(labels, out);
}

// round 8
// speedup vs baseline: 1.0324x; 1.0324x over previous
#include <cuda_runtime.h>
#include <cuda_bf16.h>
#include <math.h>
#include <stdint.h>

#define N 4096
#define D 512
#define MARGIN 0.3f
#define BIG 1000000.0f
#define NT 32                       // 4096/128 tile grid
#define NBLK (NT * (NT + 1) / 2)    // 528 upper-triangular tiles

// ---------------- scratch (no allocs allowed) ----------------
__device__ float g_dist[(size_t)N * N];            // 64 MB: squared distances (d2)
__device__ __nv_bfloat16 g_hi[(size_t)N * D];      // bf16 hi split
__device__ __nv_bfloat16 g_lo[(size_t)N * D];      // bf16 lo split
__device__ float g_sq[N];
__device__ int   g_hp_bits[N];                     // hp^2 bits (atomicMax, >0)
__device__ int   g_fb_bits[N];                     // fb^2 bits
__device__ int   g_smin_bits[N];                   // min d2 over {d2 > hp2} (atomicMin)
__device__ int   g_done;

// ---------------- PTX helpers ----------------
__device__ __forceinline__ uint32_t smem_u32(const void* p) {
    return (uint32_t)__cvta_generic_to_shared(p);
}
__device__ __forceinline__ void cp16(uint32_t dst, const void* src) {
    asm volatile("cp.async.cg.shared.global [%0], [%1], 16;" :: "r"(dst), "l"(src));
}
#define LDSM4(r0, r1, r2, r3, addr)                                          \
    asm volatile("ldmatrix.sync.aligned.m8n8.x4.shared.b16 {%0,%1,%2,%3}, [%4];" \
                 : "=r"(r0), "=r"(r1), "=r"(r2), "=r"(r3) : "r"(addr))
#define MMA_BF16(acc, a, b)                                                  \
    asm volatile("mma.sync.aligned.m16n8k16.row.col.f32.bf16.bf16.f32 "      \
                 "{%0,%1,%2,%3}, {%4,%5,%6,%7}, {%8,%9}, {%0,%1,%2,%3};"     \
                 : "+f"((acc)[0]), "+f"((acc)[1]), "+f"((acc)[2]), "+f"((acc)[3]) \
                 : "r"((a)[0]), "r"((a)[1]), "r"((a)[2]), "r"((a)[3]),       \
                   "r"((b)[0]), "r"((b)[1]))

// ---------------- 1: prep — warp-per-row bf16 split + sq-norms + init ----------------
__global__ __launch_bounds__(256) void prep_kernel(const float* __restrict__ E) {
    const int w = threadIdx.x >> 5, lane = threadIdx.x & 31;
    const int row = blockIdx.x * 8 + w;
    const float* __restrict__ src = E + (size_t)row * D;
    float s = 0.0f;
#pragma unroll
    for (int q = 0; q < 4; q++) {
        const int col = (lane + 32 * q) * 4;
        const float4 v = *(const float4*)&src[col];
        const float f[4] = {v.x, v.y, v.z, v.w};
        uint32_t hp[2], lp[2];
#pragma unroll
        for (int p = 0; p < 2; p++) {
            const float a = f[2 * p], b = f[2 * p + 1];
            s += a * a + b * b;
            const __nv_bfloat16 ha = __float2bfloat16(a);
            const __nv_bfloat16 hb = __float2bfloat16(b);
            const __nv_bfloat16 la = __float2bfloat16(a - __bfloat162float(ha));
            const __nv_bfloat16 lb = __float2bfloat16(b - __bfloat162float(hb));
            hp[p] = ((uint32_t)__bfloat16_as_ushort(hb) << 16) | __bfloat16_as_ushort(ha);
            lp[p] = ((uint32_t)__bfloat16_as_ushort(lb) << 16) | __bfloat16_as_ushort(la);
        }
        *(uint2*)&g_hi[(size_t)row * D + col] = make_uint2(hp[0], hp[1]);
        *(uint2*)&g_lo[(size_t)row * D + col] = make_uint2(lp[0], lp[1]);
    }
    for (int o = 16; o > 0; o >>= 1) s += __shfl_down_sync(0xFFFFFFFF, s, o);
    if (lane == 0) {
        g_sq[row] = s;
        g_hp_bits[row] = 0;
        g_fb_bits[row] = 0;
        g_smin_bits[row] = 0x7F7FFFFF;      // FLT_MAX bits
    }
    if (blockIdx.x == 0 && threadIdx.x == 0) g_done = 0;
}

// ---------------- 2: symmetric bf16 split-GEMM -> d2(+mirror) + fused hp2/fb2 ----------------
#define BM 128
#define BN 128
#define KS 16                    // 512 / 32
#define ROWB 80                  // 32 bf16 = 64B + 16B pad
#define TILEB (128 * ROWB)       // 10240 per tile
#define SM_LJ 0
#define SM_LI 512
#define SM_SQJ 1024
#define SM_SQI 1536
#define SM_OPS 2048
#define GEMM_SMEM (SM_OPS + 8 * TILEB)     // 83968
#define STG_STRIDE 132

__global__ __launch_bounds__(256) void gemm_bf16(const int* __restrict__ labels) {
    extern __shared__ char smem[];
    const int tid = threadIdx.x, lane = tid & 31, wid = tid >> 5;
    const int wm = wid >> 2, wn = wid & 3;          // 2 x 4 warp grid
    const int gid = lane >> 2, tig = lane & 3;

    // map linear block id -> upper-triangular tile (bi <= bj)
    int b = blockIdx.x, bi = 0;
    while (b >= NT - bi) { b -= NT - bi; bi++; }
    const int bj = bi + b;
    const int i0 = bi * BM, j0 = bj * BN;
    const bool diag = (bi == bj);

    const uint32_t sb = smem_u32(smem);
    int*   lj  = (int*)(smem + SM_LJ);
    int*   li  = (int*)(smem + SM_LI);
    float* sqj = (float*)(smem + SM_SQJ);
    float* sqi = (float*)(smem + SM_SQI);
    if (tid < 128) { lj[tid] = labels[j0 + tid]; sqj[tid] = g_sq[j0 + tid]; }
    else { const int t2 = tid - 128; li[t2] = labels[i0 + t2]; sqi[t2] = g_sq[i0 + t2]; }

    float acc[4][4][4];
#pragma unroll
    for (int mt = 0; mt < 4; mt++)
#pragma unroll
        for (int nt = 0; nt < 4; nt++)
#pragma unroll
            for (int k = 0; k < 4; k++) acc[mt][nt][k] = 0.0f;

    auto load_stage = [&](int st, int k0e) {
        const uint32_t base = sb + SM_OPS + ((st & 1) ? 4 * TILEB : 0);
#pragma unroll
        for (int i = 0; i < 8; i++) {
            const int idx = tid + i * 256;
            const int tile = idx >> 9;          // 0:Ah 1:Al 2:Bh 3:Bl
            const int id = idx & 511;
            const int r = id >> 2, c = id & 3;
            const int grow = ((tile >= 2) ? j0 : i0) + r;
            const __nv_bfloat16* src =
                ((tile & 1) ? g_lo : g_hi) + (size_t)grow * D + k0e + c * 8;
            cp16(base + tile * TILEB + r * ROWB + c * 16, src);
        }
    };

    load_stage(0, 0);
    asm volatile("cp.async.commit_group;" ::: "memory");

    for (int t = 0; t < KS; t++) {
        if (t + 1 < KS) {
            load_stage(t + 1, (t + 1) * 32);
            asm volatile("cp.async.commit_group;" ::: "memory");
            asm volatile("cp.async.wait_group 1;" ::: "memory");
        } else {
            asm volatile("cp.async.wait_group 0;" ::: "memory");
        }
        __syncthreads();

        const uint32_t base = sb + SM_OPS + ((t & 1) ? 4 * TILEB : 0);
        const uint32_t Ah = base, Al = base + TILEB;
        const uint32_t Bh = base + 2 * TILEB, Bl = base + 3 * TILEB;
        const uint32_t arow = (wm * 64 + (lane & 15)) * ROWB + (lane >> 4) * 16;
        const uint32_t brow = (wn * 32 + (lane & 15)) * ROWB + (lane >> 4) * 16;

#pragma unroll
        for (int kk = 0; kk < 2; kk++) {
            uint32_t ah[4][4], al_[4][4], bh[4][2], bl[4][2];
#pragma unroll
            for (int mt = 0; mt < 4; mt++) {
                const uint32_t off = arow + mt * 16 * ROWB + kk * 32;
                LDSM4(ah[mt][0], ah[mt][1], ah[mt][2], ah[mt][3], Ah + off);
                LDSM4(al_[mt][0], al_[mt][1], al_[mt][2], al_[mt][3], Al + off);
            }
#pragma unroll
            for (int p = 0; p < 2; p++) {
                const uint32_t off = brow + p * 16 * ROWB + kk * 32;
                uint32_t r0, r1, r2, r3;
                LDSM4(r0, r1, r2, r3, Bh + off);
                bh[p * 2][0] = r0; bh[p * 2][1] = r2;
                bh[p * 2 + 1][0] = r1; bh[p * 2 + 1][1] = r3;
                LDSM4(r0, r1, r2, r3, Bl + off);
                bl[p * 2][0] = r0; bl[p * 2][1] = r2;
                bl[p * 2 + 1][0] = r1; bl[p * 2 + 1][1] = r3;
            }
#pragma unroll
            for (int mt = 0; mt < 4; mt++)
#pragma unroll
                for (int nt = 0; nt < 4; nt++) {
                    MMA_BF16(acc[mt][nt], ah[mt], bh[nt]);   // hi*hi
                    MMA_BF16(acc[mt][nt], ah[mt], bl[nt]);   // hi*lo
                    MMA_BF16(acc[mt][nt], al_[mt], bh[nt]);  // lo*hi
                }
        }
        __syncthreads();
    }

    // ---- stage fp32 dots to smem (read-only afterwards) ----
    float* stg = (float*)(smem + SM_OPS);
#pragma unroll
    for (int mt = 0; mt < 4; mt++)
#pragma unroll
        for (int nt = 0; nt < 4; nt++) {
            const int r0 = wm * 64 + mt * 16 + gid;
            const int c0 = wn * 32 + nt * 8 + tig * 2;
            *(float2*)&stg[r0 * STG_STRIDE + c0] = make_float2(acc[mt][nt][0], acc[mt][nt][1]);
            *(float2*)&stg[(r0 + 8) * STG_STRIDE + c0] = make_float2(acc[mt][nt][2], acc[mt][nt][3]);
        }
    __syncthreads();

    // ---- row pass: d2, write [i,j] block, hp2/fb2 for i-rows ----
#pragma unroll 1
    for (int rr = 0; rr < 16; rr++) {
        const int row = wid * 16 + rr;
        const float4 v = *(const float4*)&stg[row * STG_STRIDE + lane * 4];
        const float sqiv = sqi[row];
        const int liv = li[row];
        float hp = 0.0f, fb = 0.0f;
        float o[4];
#pragma unroll
        for (int u = 0; u < 4; u++) {
            const int jc = lane * 4 + u;
            const float d2 = fmaxf(fmaf(-2.0f, (&v.x)[u], sqiv + sqj[jc]), 1e-12f);
            o[u] = d2;
            if (lj[jc] == liv) hp = fmaxf(hp, d2);
            else               fb = fmaxf(fb, d2);
        }
        *(float4*)&g_dist[(size_t)(i0 + row) * N + j0 + lane * 4] =
            make_float4(o[0], o[1], o[2], o[3]);
#pragma unroll
        for (int off = 16; off > 0; off >>= 1) {
            hp = fmaxf(hp, __shfl_down_sync(0xFFFFFFFF, hp, off));
            fb = fmaxf(fb, __shfl_down_sync(0xFFFFFFFF, fb, off));
        }
        if (lane == 0) {
            atomicMax(&g_hp_bits[i0 + row], __float_as_int(hp));
            atomicMax(&g_fb_bits[i0 + row], __float_as_int(fb));
        }
    }

    // ---- mirror pass (off-diagonal): recompute d2 from dots, write [j,i], hp/fb ----
    if (!diag) {
#pragma unroll 1
        for (int rr = 0; rr < 16; rr++) {
            const int jrow = wid * 16 + rr;       // row within j-tile
            const int ljv = lj[jrow];
            const float sqjv = sqj[jrow];
            float hp = 0.0f, fb = 0.0f;
#pragma unroll
            for (int u = 0; u < 4; u++) {
                const int il = lane + 32 * u;     // column within i-tile
                const float dot = stg[il * STG_STRIDE + jrow];
                const float d2 = fmaxf(fmaf(-2.0f, dot, sqi[il] + sqjv), 1e-12f);
                if (li[il] == ljv) hp = fmaxf(hp, d2);
                else               fb = fmaxf(fb, d2);
                g_dist[(size_t)(j0 + jrow) * N + i0 + il] = d2;
            }
#pragma unroll
            for (int off = 16; off > 0; off >>= 1) {
                hp = fmaxf(hp, __shfl_down_sync(0xFFFFFFFF, hp, off));
                fb = fmaxf(fb, __shfl_down_sync(0xFFFFFFFF, fb, off));
            }
            if (lane == 0) {
                atomicMax(&g_hp_bits[j0 + jrow], __float_as_int(hp));
                atomicMax(&g_fb_bits[j0 + jrow], __float_as_int(fb));
            }
        }
    }
}

// ---------------- 3: lean scan — min over {d2 > hp2}; window check at finalize ----------------
#define RPB 8     // rows per block
__global__ __launch_bounds__(256) void rowstats3(float* __restrict__ out) {
    const int t = threadIdx.x, lane = t & 31;

#pragma unroll 1
    for (int r = 0; r < RPB; r++) {
        const int i = blockIdx.x * RPB + r;
        const float hp2v = __int_as_float(g_hp_bits[i]);
        const float4* __restrict__ row4 = (const float4*)&g_dist[(size_t)i * N];

        // min over all d2 strictly above hp2 (positives are automatically excluded:
        // hp2 is the max over positives). 2 ops/element.
        float mins = 3.4e38f;
#pragma unroll 1
        for (int j4 = t; j4 < N / 4; j4 += 256) {
            const float4 v = row4[j4];
            if (v.x > hp2v) mins = fminf(mins, v.x);
            if (v.y > hp2v) mins = fminf(mins, v.y);
            if (v.z > hp2v) mins = fminf(mins, v.z);
            if (v.w > hp2v) mins = fminf(mins, v.w);
        }
#pragma unroll
        for (int off = 16; off > 0; off >>= 1)
            mins = fminf(mins, __shfl_down_sync(0xFFFFFFFF, mins, off));
        if (lane == 0)
            atomicMin(&g_smin_bits[i], __float_as_int(mins));
    }

    // ---- done counter; last block computes the loss ----
    __threadfence();
    __syncthreads();
    __shared__ int s_last;
    if (t == 0) s_last = (atomicAdd(&g_done, 1) == (N / RPB) - 1) ? 1 : 0;
    __syncthreads();
    if (!s_last) return;
    __threadfence();

    __shared__ double rs[256], rf[256];
    __shared__ int rcs[256], rcf[256], rany[256];
    double ss = 0.0, sf = 0.0;
    int cs = 0, cf = 0, any = 0;
    for (int i = t; i < N; i += 256) {
        const float hp2 = __int_as_float(g_hp_bits[i]);
        const float hpv = sqrtf(hp2);
        const float hib = hpv + MARGIN;
        const float m2 = __int_as_float(g_smin_bits[i]);
        const bool has = (m2 < hib * hib);          // min above hp2 inside window?
        any |= has ? 1 : 0;
        const float hns = has ? sqrtf(m2) : BIG;
        const float fbv = sqrtf(__int_as_float(g_fb_bits[i]));
        const float trs = fmaxf(hpv - hns + MARGIN, 0.0f);
        const float trf = fmaxf(hpv - fbv + MARGIN, 0.0f);
        ss += (double)trs; cs += (trs > 0.0f) ? 1 : 0;
        sf += (double)trf; cf += (trf > 0.0f) ? 1 : 0;
    }
    rs[t] = ss; rf[t] = sf; rcs[t] = cs; rcf[t] = cf; rany[t] = any;
    __syncthreads();
    for (int s = 128; s > 0; s >>= 1) {
        if (t < s) {
            rs[t] += rs[t + s]; rf[t] += rf[t + s];
            rcs[t] += rcs[t + s]; rcf[t] += rcf[t + s];
            rany[t] |= rany[t + s];
        }
        __syncthreads();
    }
    if (t == 0) {
        const bool semi = rany[0] != 0;
        const double s = semi ? rs[0] : rf[0];
        const int c = semi ? rcs[0] : rcf[0];
        out[0] = (float)(s / (double)(c > 0 ? c : 1));
    }
}

// ---------------- launcher ----------------
extern "C" void kernel_launch(void* const* d_in, const int* in_sizes, int n_in,
                              void* d_out, int out_size) {
    const float* E = (const float*)d_in[0];
    const int* labels = (const int*)d_in[1];
    float* out = (float*)d_out;

    cudaFuncSetAttribute(gemm_bf16, cudaFuncAttributeMaxDynamicSharedMemorySize, GEMM_SMEM);

    prep_kernel<<<N / 8, 256>>>(E);
    gemm_bf16<<<NBLK, 256, GEMM_SMEM>>>(labels);
    rowstats3<<<N / RPB, 256>>>(out);
}

// round 9
// speedup vs baseline: 1.1330x; 1.0975x over previous
#include <cuda_runtime.h>
#include <cuda_bf16.h>
#include <math.h>
#include <stdint.h>

#define N 4096
#define D 512
#define MARGIN 0.3f
#define BIG 1000000.0f
#define NT 32                       // 4096/128 tile grid
#define NBLK (NT * (NT + 1) / 2)    // 528 upper-triangular tiles

// ---------------- scratch (no allocs allowed) ----------------
__device__ float g_dist[(size_t)N * N];            // 64 MB: squared distances (d2)
__device__ __nv_bfloat16 g_hi[(size_t)N * D];      // bf16 hi split
__device__ __nv_bfloat16 g_lo[(size_t)N * D];      // bf16 lo split
__device__ float g_sq[N];
__device__ int   g_hp_bits[N];                     // hp^2 bits (atomicMax, >0)
__device__ int   g_fb_bits[N];                     // fb^2 bits
__device__ int   g_smin_bits[N];                   // min d2 over {d2 > hp2} (atomicMin)
__device__ int   g_done;

// ---------------- PTX helpers ----------------
__device__ __forceinline__ uint32_t smem_u32(const void* p) {
    return (uint32_t)__cvta_generic_to_shared(p);
}
__device__ __forceinline__ void cp16(uint32_t dst, const void* src) {
    asm volatile("cp.async.cg.shared.global [%0], [%1], 16;" :: "r"(dst), "l"(src));
}
#define LDSM4(r0, r1, r2, r3, addr)                                          \
    asm volatile("ldmatrix.sync.aligned.m8n8.x4.shared.b16 {%0,%1,%2,%3}, [%4];" \
                 : "=r"(r0), "=r"(r1), "=r"(r2), "=r"(r3) : "r"(addr))
#define MMA_BF16(acc, a, b)                                                  \
    asm volatile("mma.sync.aligned.m16n8k16.row.col.f32.bf16.bf16.f32 "      \
                 "{%0,%1,%2,%3}, {%4,%5,%6,%7}, {%8,%9}, {%0,%1,%2,%3};"     \
                 : "+f"((acc)[0]), "+f"((acc)[1]), "+f"((acc)[2]), "+f"((acc)[3]) \
                 : "r"((a)[0]), "r"((a)[1]), "r"((a)[2]), "r"((a)[3]),       \
                   "r"((b)[0]), "r"((b)[1]))

// ---------------- 1: prep — warp-per-row bf16 split + sq-norms + init ----------------
__global__ __launch_bounds__(256) void prep_kernel(const float* __restrict__ E) {
    const int w = threadIdx.x >> 5, lane = threadIdx.x & 31;
    const int row = blockIdx.x * 8 + w;
    const float* __restrict__ src = E + (size_t)row * D;
    float s = 0.0f;
#pragma unroll
    for (int q = 0; q < 4; q++) {
        const int col = (lane + 32 * q) * 4;
        const float4 v = *(const float4*)&src[col];
        const float f[4] = {v.x, v.y, v.z, v.w};
        uint32_t hp[2], lp[2];
#pragma unroll
        for (int p = 0; p < 2; p++) {
            const float a = f[2 * p], b = f[2 * p + 1];
            s += a * a + b * b;
            const __nv_bfloat16 ha = __float2bfloat16(a);
            const __nv_bfloat16 hb = __float2bfloat16(b);
            const __nv_bfloat16 la = __float2bfloat16(a - __bfloat162float(ha));
            const __nv_bfloat16 lb = __float2bfloat16(b - __bfloat162float(hb));
            hp[p] = ((uint32_t)__bfloat16_as_ushort(hb) << 16) | __bfloat16_as_ushort(ha);
            lp[p] = ((uint32_t)__bfloat16_as_ushort(lb) << 16) | __bfloat16_as_ushort(la);
        }
        *(uint2*)&g_hi[(size_t)row * D + col] = make_uint2(hp[0], hp[1]);
        *(uint2*)&g_lo[(size_t)row * D + col] = make_uint2(lp[0], lp[1]);
    }
    for (int o = 16; o > 0; o >>= 1) s += __shfl_down_sync(0xFFFFFFFF, s, o);
    if (lane == 0) {
        g_sq[row] = s;
        g_hp_bits[row] = 0;
        g_fb_bits[row] = 0;
        g_smin_bits[row] = 0x7F7FFFFF;      // FLT_MAX bits
    }
    if (blockIdx.x == 0 && threadIdx.x == 0) g_done = 0;
}

// ---------------- 2: symmetric bf16 split-GEMM -> d2(+mirror) + fused hp2/fb2 ----------------
#define BM 128
#define BN 128
#define KS 16                    // 512 / 32
#define ROWB 80                  // 32 bf16 = 64B + 16B pad
#define TILEB (128 * ROWB)       // 10240 per tile
#define SM_LJ 0
#define SM_LI 512
#define SM_SQJ 1024
#define SM_SQI 1536
#define SM_OPS 2048
#define GEMM_SMEM (SM_OPS + 8 * TILEB)     // 83968
#define STG_STRIDE 132

__global__ __launch_bounds__(256) void gemm_bf16(const int* __restrict__ labels) {
    extern __shared__ char smem[];
    const int tid = threadIdx.x, lane = tid & 31, wid = tid >> 5;
    const int wm = wid >> 2, wn = wid & 3;          // 2 x 4 warp grid
    const int gid = lane >> 2, tig = lane & 3;

    // map linear block id -> upper-triangular tile (bi <= bj)
    int b = blockIdx.x, bi = 0;
    while (b >= NT - bi) { b -= NT - bi; bi++; }
    const int bj = bi + b;
    const int i0 = bi * BM, j0 = bj * BN;
    const bool diag = (bi == bj);

    const uint32_t sb = smem_u32(smem);
    int*   lj  = (int*)(smem + SM_LJ);
    int*   li  = (int*)(smem + SM_LI);
    float* sqj = (float*)(smem + SM_SQJ);
    float* sqi = (float*)(smem + SM_SQI);
    if (tid < 128) { lj[tid] = labels[j0 + tid]; sqj[tid] = g_sq[j0 + tid]; }
    else { const int t2 = tid - 128; li[t2] = labels[i0 + t2]; sqi[t2] = g_sq[i0 + t2]; }

    float acc[4][4][4];
#pragma unroll
    for (int mt = 0; mt < 4; mt++)
#pragma unroll
        for (int nt = 0; nt < 4; nt++)
#pragma unroll
            for (int k = 0; k < 4; k++) acc[mt][nt][k] = 0.0f;

    auto load_stage = [&](int st, int k0e) {
        const uint32_t base = sb + SM_OPS + ((st & 1) ? 4 * TILEB : 0);
#pragma unroll
        for (int i = 0; i < 8; i++) {
            const int idx = tid + i * 256;
            const int tile = idx >> 9;          // 0:Ah 1:Al 2:Bh 3:Bl
            const int id = idx & 511;
            const int r = id >> 2, c = id & 3;
            const int grow = ((tile >= 2) ? j0 : i0) + r;
            const __nv_bfloat16* src =
                ((tile & 1) ? g_lo : g_hi) + (size_t)grow * D + k0e + c * 8;
            cp16(base + tile * TILEB + r * ROWB + c * 16, src);
        }
    };

    load_stage(0, 0);
    asm volatile("cp.async.commit_group;" ::: "memory");

    for (int t = 0; t < KS; t++) {
        if (t + 1 < KS) {
            load_stage(t + 1, (t + 1) * 32);
            asm volatile("cp.async.commit_group;" ::: "memory");
            asm volatile("cp.async.wait_group 1;" ::: "memory");
        } else {
            asm volatile("cp.async.wait_group 0;" ::: "memory");
        }
        __syncthreads();

        const uint32_t base = sb + SM_OPS + ((t & 1) ? 4 * TILEB : 0);
        const uint32_t Ah = base, Al = base + TILEB;
        const uint32_t Bh = base + 2 * TILEB, Bl = base + 3 * TILEB;
        const uint32_t arow = (wm * 64 + (lane & 15)) * ROWB + (lane >> 4) * 16;
        const uint32_t brow = (wn * 32 + (lane & 15)) * ROWB + (lane >> 4) * 16;

#pragma unroll
        for (int kk = 0; kk < 2; kk++) {
            uint32_t ah[4][4], al_[4][4], bh[4][2], bl[4][2];
#pragma unroll
            for (int mt = 0; mt < 4; mt++) {
                const uint32_t off = arow + mt * 16 * ROWB + kk * 32;
                LDSM4(ah[mt][0], ah[mt][1], ah[mt][2], ah[mt][3], Ah + off);
                LDSM4(al_[mt][0], al_[mt][1], al_[mt][2], al_[mt][3], Al + off);
            }
#pragma unroll
            for (int p = 0; p < 2; p++) {
                const uint32_t off = brow + p * 16 * ROWB + kk * 32;
                uint32_t r0, r1, r2, r3;
                LDSM4(r0, r1, r2, r3, Bh + off);
                bh[p * 2][0] = r0; bh[p * 2][1] = r2;
                bh[p * 2 + 1][0] = r1; bh[p * 2 + 1][1] = r3;
                LDSM4(r0, r1, r2, r3, Bl + off);
                bl[p * 2][0] = r0; bl[p * 2][1] = r2;
                bl[p * 2 + 1][0] = r1; bl[p * 2 + 1][1] = r3;
            }
#pragma unroll
            for (int mt = 0; mt < 4; mt++)
#pragma unroll
                for (int nt = 0; nt < 4; nt++) {
                    MMA_BF16(acc[mt][nt], ah[mt], bh[nt]);   // hi*hi
                    MMA_BF16(acc[mt][nt], ah[mt], bl[nt]);   // hi*lo
                    MMA_BF16(acc[mt][nt], al_[mt], bh[nt]);  // lo*hi
                }
        }
        __syncthreads();
    }

    // ---- stage fp32 dots to smem (read-only afterwards) ----
    float* stg = (float*)(smem + SM_OPS);
#pragma unroll
    for (int mt = 0; mt < 4; mt++)
#pragma unroll
        for (int nt = 0; nt < 4; nt++) {
            const int r0 = wm * 64 + mt * 16 + gid;
            const int c0 = wn * 32 + nt * 8 + tig * 2;
            *(float2*)&stg[r0 * STG_STRIDE + c0] = make_float2(acc[mt][nt][0], acc[mt][nt][1]);
            *(float2*)&stg[(r0 + 8) * STG_STRIDE + c0] = make_float2(acc[mt][nt][2], acc[mt][nt][3]);
        }
    __syncthreads();

    // ---- row pass: d2, write [i,j] block, hp2/fb2 for i-rows ----
#pragma unroll 1
    for (int rr = 0; rr < 16; rr++) {
        const int row = wid * 16 + rr;
        const float4 v = *(const float4*)&stg[row * STG_STRIDE + lane * 4];
        const float sqiv = sqi[row];
        const int liv = li[row];
        float hp = 0.0f, fb = 0.0f;
        float o[4];
#pragma unroll
        for (int u = 0; u < 4; u++) {
            const int jc = lane * 4 + u;
            const float d2 = fmaxf(fmaf(-2.0f, (&v.x)[u], sqiv + sqj[jc]), 1e-12f);
            o[u] = d2;
            if (lj[jc] == liv) hp = fmaxf(hp, d2);
            else               fb = fmaxf(fb, d2);
        }
        *(float4*)&g_dist[(size_t)(i0 + row) * N + j0 + lane * 4] =
            make_float4(o[0], o[1], o[2], o[3]);
#pragma unroll
        for (int off = 16; off > 0; off >>= 1) {
            hp = fmaxf(hp, __shfl_down_sync(0xFFFFFFFF, hp, off));
            fb = fmaxf(fb, __shfl_down_sync(0xFFFFFFFF, fb, off));
        }
        if (lane == 0) {
            atomicMax(&g_hp_bits[i0 + row], __float_as_int(hp));
            atomicMax(&g_fb_bits[i0 + row], __float_as_int(fb));
        }
    }

    // ---- mirror pass (off-diagonal): recompute d2 from dots, write [j,i], hp/fb ----
    if (!diag) {
#pragma unroll 1
        for (int rr = 0; rr < 16; rr++) {
            const int jrow = wid * 16 + rr;       // row within j-tile
            const int ljv = lj[jrow];
            const float sqjv = sqj[jrow];
            float hp = 0.0f, fb = 0.0f;
#pragma unroll
            for (int u = 0; u < 4; u++) {
                const int il = lane + 32 * u;     // column within i-tile
                const float dot = stg[il * STG_STRIDE + jrow];
                const float d2 = fmaxf(fmaf(-2.0f, dot, sqi[il] + sqjv), 1e-12f);
                if (li[il] == ljv) hp = fmaxf(hp, d2);
                else               fb = fmaxf(fb, d2);
                g_dist[(size_t)(j0 + jrow) * N + i0 + il] = d2;
            }
#pragma unroll
            for (int off = 16; off > 0; off >>= 1) {
                hp = fmaxf(hp, __shfl_down_sync(0xFFFFFFFF, hp, off));
                fb = fmaxf(fb, __shfl_down_sync(0xFFFFFFFF, fb, off));
            }
            if (lane == 0) {
                atomicMax(&g_hp_bits[j0 + jrow], __float_as_int(hp));
                atomicMax(&g_fb_bits[j0 + jrow], __float_as_int(fb));
            }
        }
    }
}

// ---------------- 3: lean scan, full MLP — min over {d2 > hp2} ----------------
#define RPB 4     // rows per block, 1024 blocks
__global__ __launch_bounds__(256) void rowstats4(float* __restrict__ out) {
    const int t = threadIdx.x, lane = t & 31;

#pragma unroll 1
    for (int r = 0; r < RPB; r++) {
        const int i = blockIdx.x * RPB + r;
        const float hp2v = __int_as_float(g_hp_bits[i]);
        const float4* __restrict__ row4 = (const float4*)&g_dist[(size_t)i * N];

        // 4 independent float4 loads issued back-to-back (MLP=4 per thread).
        const float4 v0 = row4[t];
        const float4 v1 = row4[t + 256];
        const float4 v2 = row4[t + 512];
        const float4 v3 = row4[t + 768];

        float m0 = 3.4e38f, m1 = 3.4e38f, m2 = 3.4e38f, m3 = 3.4e38f;
        if (v0.x > hp2v) m0 = v0.x;
        if (v0.y > hp2v) m1 = v0.y;
        if (v0.z > hp2v) m2 = v0.z;
        if (v0.w > hp2v) m3 = v0.w;
        if (v1.x > hp2v) m0 = fminf(m0, v1.x);
        if (v1.y > hp2v) m1 = fminf(m1, v1.y);
        if (v1.z > hp2v) m2 = fminf(m2, v1.z);
        if (v1.w > hp2v) m3 = fminf(m3, v1.w);
        if (v2.x > hp2v) m0 = fminf(m0, v2.x);
        if (v2.y > hp2v) m1 = fminf(m1, v2.y);
        if (v2.z > hp2v) m2 = fminf(m2, v2.z);
        if (v2.w > hp2v) m3 = fminf(m3, v2.w);
        if (v3.x > hp2v) m0 = fminf(m0, v3.x);
        if (v3.y > hp2v) m1 = fminf(m1, v3.y);
        if (v3.z > hp2v) m2 = fminf(m2, v3.z);
        if (v3.w > hp2v) m3 = fminf(m3, v3.w);

        float mins = fminf(fminf(m0, m1), fminf(m2, m3));
#pragma unroll
        for (int off = 16; off > 0; off >>= 1)
            mins = fminf(mins, __shfl_down_sync(0xFFFFFFFF, mins, off));
        if (lane == 0)
            atomicMin(&g_smin_bits[i], __float_as_int(mins));
    }

    // ---- done counter; last block computes the loss ----
    __threadfence();
    __syncthreads();
    __shared__ int s_last;
    if (t == 0) s_last = (atomicAdd(&g_done, 1) == (N / RPB) - 1) ? 1 : 0;
    __syncthreads();
    if (!s_last) return;
    __threadfence();

    __shared__ double rs[256], rf[256];
    __shared__ int rcs[256], rcf[256], rany[256];
    double ss = 0.0, sf = 0.0;
    int cs = 0, cf = 0, any = 0;
    for (int i = t; i < N; i += 256) {
        const float hp2 = __int_as_float(g_hp_bits[i]);
        const float hpv = sqrtf(hp2);
        const float hib = hpv + MARGIN;
        const float m2 = __int_as_float(g_smin_bits[i]);
        const bool has = (m2 < hib * hib);          // min above hp2 inside window?
        any |= has ? 1 : 0;
        const float hns = has ? sqrtf(m2) : BIG;
        const float fbv = sqrtf(__int_as_float(g_fb_bits[i]));
        const float trs = fmaxf(hpv - hns + MARGIN, 0.0f);
        const float trf = fmaxf(hpv - fbv + MARGIN, 0.0f);
        ss += (double)trs; cs += (trs > 0.0f) ? 1 : 0;
        sf += (double)trf; cf += (trf > 0.0f) ? 1 : 0;
    }
    rs[t] = ss; rf[t] = sf; rcs[t] = cs; rcf[t] = cf; rany[t] = any;
    __syncthreads();
    for (int s = 128; s > 0; s >>= 1) {
        if (t < s) {
            rs[t] += rs[t + s]; rf[t] += rf[t + s];
            rcs[t] += rcs[t + s]; rcf[t] += rcf[t + s];
            rany[t] |= rany[t + s];
        }
        __syncthreads();
    }
    if (t == 0) {
        const bool semi = rany[0] != 0;
        const double s = semi ? rs[0] : rf[0];
        const int c = semi ? rcs[0] : rcf[0];
        out[0] = (float)(s / (double)(c > 0 ? c : 1));
    }
}

// ---------------- launcher ----------------
extern "C" void kernel_launch(void* const* d_in, const int* in_sizes, int n_in,
                              void* d_out, int out_size) {
    const float* E = (const float*)d_in[0];
    const int* labels = (const int*)d_in[1];
    float* out = (float*)d_out;

    cudaFuncSetAttribute(gemm_bf16, cudaFuncAttributeMaxDynamicSharedMemorySize, GEMM_SMEM);

    prep_kernel<<<N / 8, 256>>>(E);
    gemm_bf16<<<NBLK, 256, GEMM_SMEM>>>(labels);
    rowstats4<<<N / RPB, 256>>>(out);
}